// round 3
// baseline (speedup 1.0000x reference)
#include <cuda_runtime.h>
#include <math.h>
#include <stdint.h>

#define Bc 16
#define Sc 512
#define Dc 1024
#define Hc 8
#define DFFc 4096
#define DKc 128
#define MROWS (Bc*Sc)
#define NEGF (-1e32f)

// ---------------- scratch (device globals; no allocation allowed) ----------------
__device__ float g_y[(size_t)MROWS*Dc];
__device__ float g_xb[(size_t)MROWS*Dc];
__device__ float g_cat[(size_t)MROWS*Dc];
__device__ float g_proj[(size_t)MROWS*Dc];
__device__ float g_qk[(size_t)MROWS*Dc];
__device__ float g_v[(size_t)MROWS*Dc];     // head-transposed: [B,H,DK,S]
__device__ float g_att[(size_t)MROWS*Dc];
__device__ float g_scores[(size_t)Bc*Hc*Sc*Sc];
__device__ float g_ff[(size_t)MROWS*DFFc];
__device__ int   g_ext[Hc*Sc];

__device__ __forceinline__ uint32_t cvt_tf32(float x) {
    uint32_t r;
    asm("cvt.rna.tf32.f32 %0, %1;" : "=r"(r) : "f"(x));
    return r;
}

// ---------------- TF32 tensor-core GEMM: C = alpha*A(M,K)@B(N,K)^T + bias -------
// Block tile 128x128, BK=16, 4 warps (64x64 each), mma.m16n8k8, double-buffered.
__global__ __launch_bounds__(128, 2)
void gemm_tf32(const float* __restrict__ A, const float* __restrict__ Bm,
               const float* __restrict__ bias, float* __restrict__ C,
               int M, int N, int K,
               long sA, long sB, long sC, float alpha, int relu)
{
    __shared__ float As[2][128*16];
    __shared__ float Bs[2][128*16];

    const int tid = threadIdx.x;
    const int warp = tid >> 5, lane = tid & 31;
    const int wm = warp >> 1, wn = warp & 1;      // 2x2 warp grid
    const int gid = lane >> 2, tig = lane & 3;

    const float* Ab = A + (long)blockIdx.z * sA + (long)blockIdx.y * 128 * K;
    const float* Bb = Bm + (long)blockIdx.z * sB + (long)blockIdx.x * 128 * K;

    float acc[4][8][4];
#pragma unroll
    for (int t = 0; t < 4; t++)
#pragma unroll
        for (int u = 0; u < 8; u++)
#pragma unroll
            for (int r = 0; r < 4; r++) acc[t][u][r] = 0.f;

    // loader mapping: 512 float4 per 128x16 tile, 4 per thread
    int lm[4], soff[4];
    long goff[4];
#pragma unroll
    for (int q = 0; q < 4; q++) {
        int idx = q * 128 + tid;
        int m = idx >> 2, c = idx & 3;
        lm[q] = m;
        goff[q] = (long)m * K + c * 4;
        soff[q] = m * 16 + (c ^ ((m >> 1) & 3)) * 4;
    }

    // ldmatrix per-thread row/chunk components
    const int lr8 = lane & 7;
    const int selA_row = ((lane >> 3) & 1) * 8;   // a: sel&1 -> +8 rows
    const int selA_k   = ((lane >> 4) & 1) * 4;   // a: sel>>1 -> +4 k
    const int selB_row = ((lane >> 4) & 1) * 8;   // b: sel>>1 -> +8 rows
    const int selB_k   = ((lane >> 3) & 1) * 4;   // b: sel&1 -> +4 k

    float4 ra[4], rb[4];
    // prologue: load k0=0
#pragma unroll
    for (int q = 0; q < 4; q++) {
        ra[q] = *(const float4*)(Ab + goff[q]);
        rb[q] = *(const float4*)(Bb + goff[q]);
    }
#pragma unroll
    for (int q = 0; q < 4; q++) {
        uint32_t* pa = (uint32_t*)&As[0][soff[q]];
        pa[0] = cvt_tf32(ra[q].x); pa[1] = cvt_tf32(ra[q].y);
        pa[2] = cvt_tf32(ra[q].z); pa[3] = cvt_tf32(ra[q].w);
        uint32_t* pb = (uint32_t*)&Bs[0][soff[q]];
        pb[0] = cvt_tf32(rb[q].x); pb[1] = cvt_tf32(rb[q].y);
        pb[2] = cvt_tf32(rb[q].z); pb[3] = cvt_tf32(rb[q].w);
    }
    __syncthreads();

    int nbuf = 0;
    for (int k0 = 0; k0 < K; k0 += 16) {
        if (k0 + 16 < K) {
#pragma unroll
            for (int q = 0; q < 4; q++) {
                ra[q] = *(const float4*)(Ab + goff[q] + k0 + 16);
                rb[q] = *(const float4*)(Bb + goff[q] + k0 + 16);
            }
        }

        uint32_t abase = (uint32_t)__cvta_generic_to_shared(&As[nbuf][0]);
        uint32_t bbase = (uint32_t)__cvta_generic_to_shared(&Bs[nbuf][0]);

#pragma unroll
        for (int ks = 0; ks < 2; ks++) {
            uint32_t a_frag[4][4], b_frag[8][2];
#pragma unroll
            for (int t = 0; t < 4; t++) {
                int row = wm * 64 + t * 16 + lr8 + selA_row;
                int chunk = (ks * 8 + selA_k) >> 2;
                int sw = chunk ^ ((row >> 1) & 3);
                uint32_t addr = abase + (uint32_t)(row * 16 + sw * 4) * 4u;
                asm volatile(
                    "ldmatrix.sync.aligned.m8n8.x4.shared.b16 {%0,%1,%2,%3}, [%4];"
                    : "=r"(a_frag[t][0]), "=r"(a_frag[t][1]),
                      "=r"(a_frag[t][2]), "=r"(a_frag[t][3])
                    : "r"(addr));
            }
#pragma unroll
            for (int p = 0; p < 4; p++) {
                int row = wn * 64 + p * 16 + lr8 + selB_row;
                int chunk = (ks * 8 + selB_k) >> 2;
                int sw = chunk ^ ((row >> 1) & 3);
                uint32_t addr = bbase + (uint32_t)(row * 16 + sw * 4) * 4u;
                asm volatile(
                    "ldmatrix.sync.aligned.m8n8.x4.shared.b16 {%0,%1,%2,%3}, [%4];"
                    : "=r"(b_frag[2*p][0]), "=r"(b_frag[2*p][1]),
                      "=r"(b_frag[2*p+1][0]), "=r"(b_frag[2*p+1][1])
                    : "r"(addr));
            }
#pragma unroll
            for (int t = 0; t < 4; t++)
#pragma unroll
                for (int u = 0; u < 8; u++) {
                    asm volatile(
                        "mma.sync.aligned.m16n8k8.row.col.f32.tf32.tf32.f32 "
                        "{%0,%1,%2,%3}, {%4,%5,%6,%7}, {%8,%9}, {%0,%1,%2,%3};"
                        : "+f"(acc[t][u][0]), "+f"(acc[t][u][1]),
                          "+f"(acc[t][u][2]), "+f"(acc[t][u][3])
                        : "r"(a_frag[t][0]), "r"(a_frag[t][1]),
                          "r"(a_frag[t][2]), "r"(a_frag[t][3]),
                          "r"(b_frag[u][0]), "r"(b_frag[u][1]));
                }
        }

        if (k0 + 16 < K) {
            int ob = nbuf ^ 1;
#pragma unroll
            for (int q = 0; q < 4; q++) {
                uint32_t* pa = (uint32_t*)&As[ob][soff[q]];
                pa[0] = cvt_tf32(ra[q].x); pa[1] = cvt_tf32(ra[q].y);
                pa[2] = cvt_tf32(ra[q].z); pa[3] = cvt_tf32(ra[q].w);
                uint32_t* pb = (uint32_t*)&Bs[ob][soff[q]];
                pb[0] = cvt_tf32(rb[q].x); pb[1] = cvt_tf32(rb[q].y);
                pb[2] = cvt_tf32(rb[q].z); pb[3] = cvt_tf32(rb[q].w);
            }
        }
        __syncthreads();
        nbuf ^= 1;
    }

    float* Cb = C + (long)blockIdx.z * sC;
    const int rb0 = blockIdx.y * 128 + wm * 64;
    const int cb0 = blockIdx.x * 128 + wn * 64;
#pragma unroll
    for (int t = 0; t < 4; t++) {
        int r0 = rb0 + t * 16 + gid;
#pragma unroll
        for (int u = 0; u < 8; u++) {
            int col = cb0 + u * 8 + tig * 2;
            float b0 = 0.f, b1 = 0.f;
            if (bias) { b0 = bias[col]; b1 = bias[col + 1]; }
            float v0 = acc[t][u][0] * alpha + b0;
            float v1 = acc[t][u][1] * alpha + b1;
            float v2 = acc[t][u][2] * alpha + b0;
            float v3 = acc[t][u][3] * alpha + b1;
            if (relu) {
                v0 = fmaxf(v0, 0.f); v1 = fmaxf(v1, 0.f);
                v2 = fmaxf(v2, 0.f); v3 = fmaxf(v3, 0.f);
            }
            *(float2*)(Cb + (long)r0 * N + col)       = make_float2(v0, v1);
            *(float2*)(Cb + (long)(r0 + 8) * N + col) = make_float2(v2, v3);
        }
    }
}

// ---------------- layout reshapes ------------------------------------------------
// (B,S,D) -> (B,H,S,DK)
__global__ void to_heads(const float* __restrict__ in, float* __restrict__ out)
{
    int t = blockIdx.x * blockDim.x + threadIdx.x;
    int dq = t & (DKc/4 - 1);
    int rest = t >> 5;
    int s = rest & (Sc - 1); rest >>= 9;
    int h = rest & (Hc - 1);
    int b = rest >> 3;
    float4 v = *(const float4*)(in + ((long)(b*Sc + s) * Dc + h*DKc + dq*4));
    *(float4*)(out + (long)t * 4) = v;
}

// (B,S,D) -> (B,H,DK,S)  (head-transposed, for NT att@v)
__global__ void to_heads_t(const float* __restrict__ in, float* __restrict__ out)
{
    int t = blockIdx.x * blockDim.x + threadIdx.x;   // B*H*(DK/4)*S
    int s = t & (Sc - 1);
    int rest = t >> 9;
    int dq = rest & (DKc/4 - 1);
    rest >>= 5;
    int h = rest & (Hc - 1);
    int b = rest >> 3;
    float4 v = *(const float4*)(in + ((long)(b*Sc + s) * Dc + h*DKc + dq*4));
    long ob = ((long)((b*Hc + h)*DKc) + dq*4) * Sc + s;
    out[ob]        = v.x;
    out[ob + Sc]   = v.y;
    out[ob + 2*Sc] = v.z;
    out[ob + 3*Sc] = v.w;
}

// (B,H,S,DK) -> (B,S,D)
__global__ void from_heads(const float* __restrict__ in, float* __restrict__ out)
{
    int t = blockIdx.x * blockDim.x + threadIdx.x;
    int cq = t & (Dc/4 - 1);
    int rest = t >> 8;
    int s = rest & (Sc - 1);
    int b = rest >> 9;
    int c = cq * 4;
    int h = c / DKc;
    int d = c - h * DKc;
    float4 v = *(const float4*)(in + ((long)((b*Hc + h)*Sc + s) * DKc + d));
    *(float4*)(out + (long)t * 4) = v;
}

// ---------------- dam "ext" bits ------------------------------------------------
__global__ void compute_ext(const float* __restrict__ alphas, const float* __restrict__ E,
                            int* __restrict__ ext)
{
    int idx = blockIdx.x * blockDim.x + threadIdx.x;
    if (idx < Hc * Sc) {
        float a0 = alphas[idx*2], a1 = alphas[idx*2+1];
        float g0 = -logf(E[idx*2] + 1e-5f), g1 = -logf(E[idx*2+1] + 1e-5f);
        ext[idx] = ((a0 + g0) < (a1 + g1)) ? 1 : 0;
    }
}

// ---------------- fused dam-softmax / cumdist / decay / softmax ------------------
__global__ __launch_bounds__(512)
void attn_softmax(float* __restrict__ scores, const int* __restrict__ ext,
                  const float* __restrict__ gam, int bmask, int zero_pad)
{
    const int i = blockIdx.x, h = blockIdx.y, b = blockIdx.z;
    const int j = threadIdx.x;
    __shared__ float red[512];

    float* row = scores + ((((long)b * Hc + h) * Sc + i) * Sc);
    float raw = row[j];
    int delta = j - i; if (delta < 0) delta = -delta;
    bool causal = (j < i + bmask);
    bool dam = causal || (ext[h * Sc + delta] != 0);

    float v1 = dam ? raw : NEGF;
    red[j] = v1; __syncthreads();
    for (int off = 256; off; off >>= 1) {
        if (j < off) red[j] = fmaxf(red[j], red[j + off]);
        __syncthreads();
    }
    float mx = red[0]; __syncthreads();
    float e1 = expf(v1 - mx);
    red[j] = e1; __syncthreads();
    for (int off = 256; off; off >>= 1) {
        if (j < off) red[j] += red[j + off];
        __syncthreads();
    }
    float s1 = red[0]; __syncthreads();
    float p = e1 / s1;

    float sc = causal ? p : 0.f;
    red[j] = sc; __syncthreads();
    for (int off = 1; off < 512; off <<= 1) {
        float t = (j >= off) ? red[j - off] : 0.f;
        __syncthreads();
        red[j] += t;
        __syncthreads();
    }
    float cum = red[j];
    float tot = red[511];
    __syncthreads();

    float rem = tot - cum;
    float dist = sqrtf(fmaxf(rem * (float)delta, 0.f));
    float g = gam[h];
    float sp = (g > 20.f) ? g : log1pf(expf(g));
    float te = expf(dist * (-sp));
    te = fminf(fmaxf(te, 1e-5f), 1e5f);

    float v2 = causal ? raw * te : NEGF;
    red[j] = v2; __syncthreads();
    for (int off = 256; off; off >>= 1) {
        if (j < off) red[j] = fmaxf(red[j], red[j + off]);
        __syncthreads();
    }
    float mx2 = red[0]; __syncthreads();
    float e2 = expf(v2 - mx2);
    red[j] = e2; __syncthreads();
    for (int off = 256; off; off >>= 1) {
        if (j < off) red[j] += red[j + off];
        __syncthreads();
    }
    float s2 = red[0];
    float out = e2 / s2;
    if (zero_pad && i == 0) out = 0.f;
    row[j] = out;
}

// ---------------- residual + layernorm ------------------------------------------
__global__ __launch_bounds__(256)
void add_ln(const float* __restrict__ a, const float* __restrict__ c,
            const float* __restrict__ g, const float* __restrict__ bt,
            float* __restrict__ out)
{
    const int r = blockIdx.x;
    const long base = (long)r * Dc;
    __shared__ float red[256];
    float vals[4];
    float s = 0.f;
#pragma unroll
    for (int q = 0; q < 4; q++) {
        int cidx = threadIdx.x + q * 256;
        vals[q] = a[base + cidx] + c[base + cidx];
        s += vals[q];
    }
    red[threadIdx.x] = s; __syncthreads();
    for (int off = 128; off; off >>= 1) {
        if (threadIdx.x < off) red[threadIdx.x] += red[threadIdx.x + off];
        __syncthreads();
    }
    float mu = red[0] * (1.f / Dc); __syncthreads();
    float vs = 0.f;
#pragma unroll
    for (int q = 0; q < 4; q++) { float d = vals[q] - mu; vs += d * d; }
    red[threadIdx.x] = vs; __syncthreads();
    for (int off = 128; off; off >>= 1) {
        if (threadIdx.x < off) red[threadIdx.x] += red[threadIdx.x + off];
        __syncthreads();
    }
    float var = red[0] * (1.f / Dc);
    float inv = rsqrtf(var + 1e-5f);
#pragma unroll
    for (int q = 0; q < 4; q++) {
        int cidx = threadIdx.x + q * 256;
        out[base + cidx] = (vals[q] - mu) * inv * g[cidx] + bt[cidx];
    }
}

// ---------------- host orchestration --------------------------------------------
struct Scratch {
    float *y, *xb, *cat, *proj, *qk, *v, *att, *scores, *ff;
    int* ext;
};

static void run_layer(const float* X, const float* Vin, float* outbuf,
                      int l, int bmask, int apply_pos,
                      const float* kW, const float* kb,
                      const float* vW, const float* vb,
                      const float* oW, const float* ob,
                      const float* gammas, const float* alphas, const float* gE,
                      const float* ln1g, const float* ln1b,
                      const float* w1, const float* b1,
                      const float* w2, const float* b2,
                      const float* ln2g, const float* ln2b,
                      const Scratch& S)
{
    const long DD = (long)Dc * Dc;
    const float one = 1.0f;
    const float scl = 1.0f / sqrtf((float)DKc);

    // q(=k) projection
    gemm_tf32<<<dim3(Dc/128, MROWS/128), 128>>>(X, kW + (long)l*DD, kb + (long)l*Dc, S.cat,
                                                MROWS, Dc, Dc, 0, 0, 0, one, 0);
    to_heads<<<(MROWS*Dc/4)/256, 256>>>(S.cat, S.qk);
    // v projection (head-transposed output for NT att@v)
    gemm_tf32<<<dim3(Dc/128, MROWS/128), 128>>>(Vin, vW + (long)l*DD, vb + (long)l*Dc, S.cat,
                                                MROWS, Dc, Dc, 0, 0, 0, one, 0);
    to_heads_t<<<(MROWS*Dc/4)/256, 256>>>(S.cat, S.v);

    // scores = q @ q^T / sqrt(dk), batched over B*H
    gemm_tf32<<<dim3(Sc/128, Sc/128, Bc*Hc), 128>>>(S.qk, S.qk, nullptr, S.scores,
                                                    Sc, Sc, DKc,
                                                    (long)Sc*DKc, (long)Sc*DKc, (long)Sc*Sc,
                                                    scl, 0);

    compute_ext<<<(Hc*Sc + 255)/256, 256>>>(alphas + (long)l*Hc*Sc*2, gE + (long)l*Hc*Sc*2, S.ext);
    attn_softmax<<<dim3(Sc, Hc, Bc), 512>>>(S.scores, S.ext, gammas + (long)l*Hc, bmask, bmask == 0);

    // att = scores @ v^T (v stored [DK][S] per head -> NT), batched
    gemm_tf32<<<dim3(DKc/128, Sc/128, Bc*Hc), 128>>>(S.scores, S.v, nullptr, S.att,
                                                     Sc, DKc, Sc,
                                                     (long)Sc*Sc, (long)DKc*Sc, (long)Sc*DKc,
                                                     one, 0);
    from_heads<<<(MROWS*Dc/4)/256, 256>>>(S.att, S.cat);

    // output projection + residual LN
    gemm_tf32<<<dim3(Dc/128, MROWS/128), 128>>>(S.cat, oW + (long)l*DD, ob + (long)l*Dc, S.proj,
                                                MROWS, Dc, Dc, 0, 0, 0, one, 0);
    add_ln<<<MROWS, 256>>>(X, S.proj, ln1g + (long)l*Dc, ln1b + (long)l*Dc, outbuf);

    if (apply_pos) {
        gemm_tf32<<<dim3(DFFc/128, MROWS/128), 128>>>(outbuf, w1 + (long)l*DFFc*Dc, b1 + (long)l*DFFc, S.ff,
                                                      MROWS, DFFc, Dc, 0, 0, 0, one, 1);
        gemm_tf32<<<dim3(Dc/128, MROWS/128), 128>>>(S.ff, w2 + (long)l*Dc*DFFc, b2 + (long)l*Dc, S.proj,
                                                    MROWS, Dc, DFFc, 0, 0, 0, one, 0);
        add_ln<<<MROWS, 256>>>(outbuf, S.proj, ln2g + (long)l*Dc, ln2b + (long)l*Dc, outbuf);
    }
}

extern "C" void kernel_launch(void* const* d_in, const int* in_sizes, int n_in,
                              void* d_out, int out_size)
{
    const float* q_embed  = (const float*)d_in[0];
    const float* qa_embed = (const float*)d_in[1];
    const float* kW = (const float*)d_in[2];
    const float* kb = (const float*)d_in[3];
    const float* vW = (const float*)d_in[4];
    const float* vb = (const float*)d_in[5];
    const float* oW = (const float*)d_in[6];
    const float* ob = (const float*)d_in[7];
    const float* gammas = (const float*)d_in[8];
    const float* alphas = (const float*)d_in[9];
    const float* ln1g = (const float*)d_in[10];
    const float* ln1b = (const float*)d_in[11];
    const float* w1 = (const float*)d_in[12];
    const float* b1 = (const float*)d_in[13];
    const float* w2 = (const float*)d_in[14];
    const float* b2 = (const float*)d_in[15];
    const float* ln2g = (const float*)d_in[16];
    const float* ln2b = (const float*)d_in[17];
    const float* gE = (const float*)d_in[18];
    float* out = (float*)d_out;

    Scratch S;
    cudaGetSymbolAddress((void**)&S.y, g_y);
    cudaGetSymbolAddress((void**)&S.xb, g_xb);
    cudaGetSymbolAddress((void**)&S.cat, g_cat);
    cudaGetSymbolAddress((void**)&S.proj, g_proj);
    cudaGetSymbolAddress((void**)&S.qk, g_qk);
    cudaGetSymbolAddress((void**)&S.v, g_v);
    cudaGetSymbolAddress((void**)&S.att, g_att);
    cudaGetSymbolAddress((void**)&S.scores, g_scores);
    cudaGetSymbolAddress((void**)&S.ff, g_ff);
    cudaGetSymbolAddress((void**)&S.ext, g_ext);

    run_layer(qa_embed, qa_embed, S.y, 0, 1, 1,
              kW, kb, vW, vb, oW, ob, gammas, alphas, gE,
              ln1g, ln1b, w1, b1, w2, b2, ln2g, ln2b, S);
    run_layer(q_embed, q_embed, S.xb, 1, 1, 0,
              kW, kb, vW, vb, oW, ob, gammas, alphas, gE,
              ln1g, ln1b, w1, b1, w2, b2, ln2g, ln2b, S);
    run_layer(S.xb, S.y, out, 2, 0, 1,
              kW, kb, vW, vb, oW, ob, gammas, alphas, gE,
              ln1g, ln1b, w1, b1, w2, b2, ln2g, ln2b, S);
}

// round 5
// speedup vs baseline: 2.7993x; 2.7993x over previous
#include <cuda_runtime.h>
#include <cuda_fp16.h>
#include <math.h>
#include <stdint.h>

#define Bc 16
#define Sc 512
#define Dc 1024
#define Hc 8
#define DFFc 4096
#define DKc 128
#define MROWS (Bc*Sc)
#define NEGF (-1e32f)

// ---------------- scratch ----------------
__device__ __half g_wk_h[(size_t)3*Dc*Dc];
__device__ __half g_wv_h[(size_t)3*Dc*Dc];
__device__ __half g_wo_h[(size_t)3*Dc*Dc];
__device__ __half g_w1_h[(size_t)3*DFFc*Dc];
__device__ __half g_w2_h[(size_t)3*Dc*DFFc];
__device__ __half g_qa_h[(size_t)MROWS*Dc];
__device__ __half g_q_h[(size_t)MROWS*Dc];
__device__ float  g_y[(size_t)MROWS*Dc];
__device__ __half g_y_h[(size_t)MROWS*Dc];
__device__ float  g_xb[(size_t)MROWS*Dc];
__device__ __half g_xb_h[(size_t)MROWS*Dc];
__device__ float  g_t1[(size_t)MROWS*Dc];
__device__ __half g_t1_h[(size_t)MROWS*Dc];
__device__ float  g_cat[(size_t)MROWS*Dc];
__device__ __half g_cat_h[(size_t)MROWS*Dc];
__device__ float  g_proj[(size_t)MROWS*Dc];
__device__ __half g_qk_h[(size_t)MROWS*Dc];
__device__ __half g_v_h[(size_t)MROWS*Dc];   // [B,H,DK,S]
__device__ float  g_att[(size_t)MROWS*Dc];
__device__ float  g_scores[(size_t)Bc*Hc*Sc*Sc];
__device__ __half g_scores_h[(size_t)Bc*Hc*Sc*Sc];
__device__ __half g_ff_h[(size_t)MROWS*DFFc];
__device__ int    g_ext[Hc*Sc];

__device__ __forceinline__ void cp16(uint32_t dst, const void* src) {
    asm volatile("cp.async.cg.shared.global [%0], [%1], 16;" :: "r"(dst), "l"(src));
}
// 64B-row swizzle: byte bits [4:5] ^= bits [7:8]
#define SWZ64(x) ((x) ^ (((x) >> 3) & 0x30))

// ---- fp16 tensor GEMM: C = alpha*A(M,K)@B(N,K)^T + bias; A,B half, C float/half.
// CTA tile 128x128, BK=32, 128 threads (4 warps, 64x64 each), mma m16n8k16.
__global__ __launch_bounds__(128, 2)
void gemm_h(const __half* __restrict__ A, const __half* __restrict__ Bm,
            const float* __restrict__ bias, void* __restrict__ Cv,
            int N, int K, long sA, long sB, long sC,
            float alpha, int relu, int outHalf)
{
    __shared__ __half As[2][128*32];
    __shared__ __half Bs[2][128*32];
    const int tid = threadIdx.x, warp = tid >> 5, lane = tid & 31;
    const int wm = warp >> 1, wn = warp & 1;

    const __half* Ab = A + blockIdx.z * sA + (long)blockIdx.y * 128 * K;
    const __half* Bb = Bm + blockIdx.z * sB + (long)blockIdx.x * 128 * K;

    float acc[4][8][4];
#pragma unroll
    for (int t = 0; t < 4; t++)
#pragma unroll
        for (int u = 0; u < 8; u++)
#pragma unroll
            for (int r = 0; r < 4; r++) acc[t][u][r] = 0.f;

    const uint32_t a0base = (uint32_t)__cvta_generic_to_shared(&As[0][0]);
    const uint32_t b0base = (uint32_t)__cvta_generic_to_shared(&Bs[0][0]);

    auto ld_stage = [&](int s, int k0) {
        uint32_t ab = a0base + s * 8192, bb = b0base + s * 8192;
#pragma unroll
        for (int q = 0; q < 4; q++) {
            int idx = q * 128 + tid;
            int row = idx >> 2, c = idx & 3;
            uint32_t off = SWZ64((uint32_t)(row * 64 + c * 16));
            long gofs = (long)row * K + k0 + c * 8;
            cp16(ab + off, Ab + gofs);
            cp16(bb + off, Bb + gofs);
        }
        asm volatile("cp.async.commit_group;" ::: "memory");
    };

    const int niter = K >> 5;
    ld_stage(0, 0);
    ld_stage(1, 32);

    for (int it = 0; it < niter; ++it) {
        int s = it & 1;
        if (it == niter - 1) asm volatile("cp.async.wait_group 0;" ::: "memory");
        else                 asm volatile("cp.async.wait_group 1;" ::: "memory");
        __syncthreads();

        uint32_t ab = a0base + s * 8192, bb = b0base + s * 8192;
#pragma unroll
        for (int ks = 0; ks < 2; ks++) {
            uint32_t af[4][4], bf[8][2];
#pragma unroll
            for (int t = 0; t < 4; t++) {
                int row = wm * 64 + t * 16 + (lane & 15);
                int ch = ks * 2 + (lane >> 4);
                uint32_t ad = ab + SWZ64((uint32_t)(row * 64 + ch * 16));
                asm volatile(
                    "ldmatrix.sync.aligned.m8n8.x4.shared.b16 {%0,%1,%2,%3}, [%4];"
                    : "=r"(af[t][0]), "=r"(af[t][1]), "=r"(af[t][2]), "=r"(af[t][3])
                    : "r"(ad));
            }
#pragma unroll
            for (int p = 0; p < 4; p++) {
                int nrow = wn * 64 + p * 16 + ((lane >> 4) & 1) * 8 + (lane & 7);
                int ch = ks * 2 + ((lane >> 3) & 1);
                uint32_t bd = bb + SWZ64((uint32_t)(nrow * 64 + ch * 16));
                asm volatile(
                    "ldmatrix.sync.aligned.m8n8.x4.shared.b16 {%0,%1,%2,%3}, [%4];"
                    : "=r"(bf[2*p][0]), "=r"(bf[2*p][1]),
                      "=r"(bf[2*p+1][0]), "=r"(bf[2*p+1][1])
                    : "r"(bd));
            }
#pragma unroll
            for (int t = 0; t < 4; t++)
#pragma unroll
                for (int u = 0; u < 8; u++) {
                    asm volatile(
                        "mma.sync.aligned.m16n8k16.row.col.f32.f16.f16.f32 "
                        "{%0,%1,%2,%3}, {%4,%5,%6,%7}, {%8,%9}, {%0,%1,%2,%3};"
                        : "+f"(acc[t][u][0]), "+f"(acc[t][u][1]),
                          "+f"(acc[t][u][2]), "+f"(acc[t][u][3])
                        : "r"(af[t][0]), "r"(af[t][1]), "r"(af[t][2]), "r"(af[t][3]),
                          "r"(bf[u][0]), "r"(bf[u][1]));
                }
        }
        __syncthreads();
        if (it + 2 < niter) ld_stage(s, (it + 2) << 5);
    }

    const int rb0 = blockIdx.y * 128 + wm * 64;
    const int cb0 = blockIdx.x * 128 + wn * 64;
    const int rsub = lane >> 2, csub = (lane & 3) * 2;
#pragma unroll
    for (int t = 0; t < 4; t++) {
        int r0 = rb0 + t * 16 + rsub;
#pragma unroll
        for (int u = 0; u < 8; u++) {
            int col = cb0 + u * 8 + csub;
            float b0 = 0.f, b1 = 0.f;
            if (bias) { b0 = bias[col]; b1 = bias[col + 1]; }
            float v0 = acc[t][u][0] * alpha + b0;
            float v1 = acc[t][u][1] * alpha + b1;
            float v2 = acc[t][u][2] * alpha + b0;
            float v3 = acc[t][u][3] * alpha + b1;
            if (relu) {
                v0 = fmaxf(v0, 0.f); v1 = fmaxf(v1, 0.f);
                v2 = fmaxf(v2, 0.f); v3 = fmaxf(v3, 0.f);
            }
            if (outHalf) {
                __half* Ch = (__half*)Cv + blockIdx.z * sC;
                *(__half2*)(Ch + (long)r0 * N + col)       = __floats2half2_rn(v0, v1);
                *(__half2*)(Ch + (long)(r0 + 8) * N + col) = __floats2half2_rn(v2, v3);
            } else {
                float* Cf = (float*)Cv + blockIdx.z * sC;
                *(float2*)(Cf + (long)r0 * N + col)       = make_float2(v0, v1);
                *(float2*)(Cf + (long)(r0 + 8) * N + col) = make_float2(v2, v3);
            }
        }
    }
}

// ---------------- conversions / reshapes ----------------
__global__ void round_copy_h(const float* __restrict__ in, __half* __restrict__ out, long n4)
{
    long t = (long)blockIdx.x * blockDim.x + threadIdx.x;
    if (t < n4) {
        float4 v = ((const float4*)in)[t];
        __half2 h0 = __floats2half2_rn(v.x, v.y);
        __half2 h1 = __floats2half2_rn(v.z, v.w);
        uint2 u = make_uint2(*(uint32_t*)&h0, *(uint32_t*)&h1);
        *(uint2*)(out + t * 4) = u;
    }
}

// (B,S,D) float -> (B,H,S,DK) half
__global__ void to_heads(const float* __restrict__ in, __half* __restrict__ out)
{
    int t = blockIdx.x * blockDim.x + threadIdx.x;
    int dq = t & 31;
    int rest = t >> 5;
    int s = rest & (Sc - 1); rest >>= 9;
    int h = rest & 7;
    int b = rest >> 3;
    float4 v = *(const float4*)(in + ((long)(b*Sc + s) * Dc + h*DKc + dq*4));
    __half2 h0 = __floats2half2_rn(v.x, v.y);
    __half2 h1 = __floats2half2_rn(v.z, v.w);
    *(uint2*)(out + (long)t * 4) = make_uint2(*(uint32_t*)&h0, *(uint32_t*)&h1);
}

// (B,S,D) float -> (B,H,DK,S) half
__global__ void to_heads_t(const float* __restrict__ in, __half* __restrict__ out)
{
    int t = blockIdx.x * blockDim.x + threadIdx.x;
    int s = t & (Sc - 1);
    int rest = t >> 9;
    int dq = rest & 31;
    rest >>= 5;
    int h = rest & 7;
    int b = rest >> 3;
    float4 v = *(const float4*)(in + ((long)(b*Sc + s) * Dc + h*DKc + dq*4));
    long ob = ((long)((b*Hc + h)*DKc) + dq*4) * Sc + s;
    out[ob]        = __float2half_rn(v.x);
    out[ob + Sc]   = __float2half_rn(v.y);
    out[ob + 2*Sc] = __float2half_rn(v.z);
    out[ob + 3*Sc] = __float2half_rn(v.w);
}

// (B,H,S,DK) float -> (B,S,D) half
__global__ void from_heads(const float* __restrict__ in, __half* __restrict__ out)
{
    int t = blockIdx.x * blockDim.x + threadIdx.x;
    int cq = t & 255;
    int rest = t >> 8;
    int s = rest & (Sc - 1);
    int b = rest >> 9;
    int c = cq * 4;
    int h = c >> 7;
    int d = c & 127;
    float4 v = *(const float4*)(in + ((long)((b*Hc + h)*Sc + s) * DKc + d));
    __half2 h0 = __floats2half2_rn(v.x, v.y);
    __half2 h1 = __floats2half2_rn(v.z, v.w);
    *(uint2*)(out + (long)t * 4) = make_uint2(*(uint32_t*)&h0, *(uint32_t*)&h1);
}

__global__ void compute_ext(const float* __restrict__ alphas, const float* __restrict__ E,
                            int* __restrict__ ext)
{
    int idx = blockIdx.x * blockDim.x + threadIdx.x;
    if (idx < Hc * Sc) {
        float a0 = alphas[idx*2], a1 = alphas[idx*2+1];
        float g0 = -logf(E[idx*2] + 1e-5f), g1 = -logf(E[idx*2+1] + 1e-5f);
        ext[idx] = ((a0 + g0) < (a1 + g1)) ? 1 : 0;
    }
}

// ---------------- warp-per-row fused softmax pipeline (float in, half out) -------
__global__ __launch_bounds__(256)
void attn_softmax2(const float* __restrict__ scores, __half* __restrict__ out_h,
                   const int* __restrict__ ext, const float* __restrict__ gam,
                   int bmask, int zero_pad)
{
    const int warp = threadIdx.x >> 5, lane = threadIdx.x & 31;
    const long rid = (long)blockIdx.x * 8 + warp;
    const int i = (int)(rid & (Sc - 1));
    const int h = (int)((rid >> 9) & (Hc - 1));
    const float* row = scores + rid * Sc;
    const int j0 = lane * 16;

    float raw[16];
#pragma unroll
    for (int c = 0; c < 4; c++)
        *(float4*)&raw[c*4] = *(const float4*)(row + j0 + c*4);

    float g = gam[h];
    float sp = (g > 20.f) ? g : log1pf(expf(g));
    const int* exth = ext + h * Sc;

    float m1 = NEGF, v1[16];
#pragma unroll
    for (int c = 0; c < 16; c++) {
        int j = j0 + c;
        int d = j - i; d = d < 0 ? -d : d;
        bool causal = j < i + bmask;
        bool dam = causal || (exth[d] != 0);
        v1[c] = dam ? raw[c] : NEGF;
        m1 = fmaxf(m1, v1[c]);
    }
#pragma unroll
    for (int o = 16; o; o >>= 1) m1 = fmaxf(m1, __shfl_xor_sync(~0u, m1, o));
    float s1 = 0.f, p[16];
#pragma unroll
    for (int c = 0; c < 16; c++) { p[c] = expf(v1[c] - m1); s1 += p[c]; }
#pragma unroll
    for (int o = 16; o; o >>= 1) s1 += __shfl_xor_sync(~0u, s1, o);
    float inv1 = 1.f / s1;

    float run = 0.f, cum[16];
#pragma unroll
    for (int c = 0; c < 16; c++) {
        int j = j0 + c;
        float sc = (j < i + bmask) ? p[c] * inv1 : 0.f;
        run += sc;
        cum[c] = run;
    }
    float excl = run;
#pragma unroll
    for (int o = 1; o < 32; o <<= 1) {
        float t = __shfl_up_sync(~0u, excl, o);
        if (lane >= o) excl += t;
    }
    float tot = __shfl_sync(~0u, excl, 31);
    excl -= run;

    float m2 = NEGF, v2[16];
#pragma unroll
    for (int c = 0; c < 16; c++) {
        int j = j0 + c;
        int d = j - i; d = d < 0 ? -d : d;
        bool causal = j < i + bmask;
        float rem = tot - (excl + cum[c]);
        float dist = sqrtf(fmaxf(rem * (float)d, 0.f));
        float te = expf(dist * (-sp));
        te = fminf(fmaxf(te, 1e-5f), 1e5f);
        v2[c] = causal ? raw[c] * te : NEGF;
        m2 = fmaxf(m2, v2[c]);
    }
#pragma unroll
    for (int o = 16; o; o >>= 1) m2 = fmaxf(m2, __shfl_xor_sync(~0u, m2, o));
    float s2 = 0.f;
#pragma unroll
    for (int c = 0; c < 16; c++) { v2[c] = expf(v2[c] - m2); s2 += v2[c]; }
#pragma unroll
    for (int o = 16; o; o >>= 1) s2 += __shfl_xor_sync(~0u, s2, o);
    float inv2 = 1.f / s2;

    bool zp = (zero_pad && i == 0);
    uint32_t w[8];
#pragma unroll
    for (int c = 0; c < 8; c++) {
        float a = zp ? 0.f : v2[2*c] * inv2;
        float b = zp ? 0.f : v2[2*c+1] * inv2;
        __half2 hh = __floats2half2_rn(a, b);
        w[c] = *(uint32_t*)&hh;
    }
    __half* orow = out_h + rid * Sc + j0;
    *(uint4*)(orow)     = make_uint4(w[0], w[1], w[2], w[3]);
    *(uint4*)(orow + 8) = make_uint4(w[4], w[5], w[6], w[7]);
}

// ---------------- residual + layernorm (float out + optional half copy) ----------
__global__ __launch_bounds__(256)
void add_ln(const float* __restrict__ a, const float* __restrict__ c,
            const float* __restrict__ g, const float* __restrict__ bt,
            float* __restrict__ out, __half* __restrict__ out_h)
{
    const int r = blockIdx.x;
    const long base = (long)r * Dc;
    __shared__ float red[256];
    float vals[4];
    float s = 0.f;
#pragma unroll
    for (int q = 0; q < 4; q++) {
        int ci = threadIdx.x + q * 256;
        vals[q] = a[base + ci] + c[base + ci];
        s += vals[q];
    }
    red[threadIdx.x] = s; __syncthreads();
    for (int off = 128; off; off >>= 1) {
        if (threadIdx.x < off) red[threadIdx.x] += red[threadIdx.x + off];
        __syncthreads();
    }
    float mu = red[0] * (1.f / Dc); __syncthreads();
    float vs = 0.f;
#pragma unroll
    for (int q = 0; q < 4; q++) { float d = vals[q] - mu; vs += d * d; }
    red[threadIdx.x] = vs; __syncthreads();
    for (int off = 128; off; off >>= 1) {
        if (threadIdx.x < off) red[threadIdx.x] += red[threadIdx.x + off];
        __syncthreads();
    }
    float inv = rsqrtf(red[0] * (1.f / Dc) + 1e-5f);
#pragma unroll
    for (int q = 0; q < 4; q++) {
        int ci = threadIdx.x + q * 256;
        float o = (vals[q] - mu) * inv * g[ci] + bt[ci];
        out[base + ci] = o;
        if (out_h) out_h[base + ci] = __float2half_rn(o);
    }
}

// ---------------- host orchestration ----------------
struct Scratch {
    __half *wk, *wv, *wo, *w1, *w2;
    __half *qa_h, *q_h, *y_h, *xb_h, *t1_h, *cat_h, *qk_h, *v_h, *scores_h, *ff_h;
    float *y, *xb, *t1, *cat, *proj, *att, *scores;
    int* ext;
};

static void run_layer(const float* X, const __half* X_h, const __half* Vin_h,
                      float* outbuf, __half* outbuf_h,
                      int l, int bmask, int apply_pos,
                      const float* kb, const float* vb, const float* ob,
                      const float* gammas, const float* alphas, const float* gE,
                      const float* ln1g, const float* ln1b,
                      const float* b1, const float* b2,
                      const float* ln2g, const float* ln2b,
                      const Scratch& S)
{
    const long DD = (long)Dc * Dc;
    const float scl = 1.0f / sqrtf((float)DKc);
    const long SDK = (long)Sc * DKc;
    const long SS = (long)Sc * Sc;

    float*  ln1o   = apply_pos ? S.t1   : outbuf;
    __half* ln1o_h = apply_pos ? S.t1_h : outbuf_h;

    // q(=k) projection -> float cat -> half heads
    gemm_h<<<dim3(Dc/128, MROWS/128), 128>>>(
        X_h, S.wk + (long)l*DD, kb + (long)l*Dc, S.cat, Dc, Dc, 0, 0, 0, 1.f, 0, 0);
    to_heads<<<(MROWS*Dc/4)/256, 256>>>(S.cat, S.qk_h);
    // v projection -> half heads transposed
    gemm_h<<<dim3(Dc/128, MROWS/128), 128>>>(
        Vin_h, S.wv + (long)l*DD, vb + (long)l*Dc, S.cat, Dc, Dc, 0, 0, 0, 1.f, 0, 0);
    to_heads_t<<<(MROWS*Dc/4)/256, 256>>>(S.cat, S.v_h);

    // scores (float) = q @ q^T / sqrt(dk)
    gemm_h<<<dim3(Sc/128, Sc/128, Bc*Hc), 128>>>(
        S.qk_h, S.qk_h, nullptr, S.scores, Sc, DKc, SDK, SDK, SS, scl, 0, 0);

    compute_ext<<<(Hc*Sc + 255)/256, 256>>>(alphas + (long)l*Hc*Sc*2,
                                            gE + (long)l*Hc*Sc*2, S.ext);
    attn_softmax2<<<(Bc*Hc*Sc)/8, 256>>>(S.scores, S.scores_h, S.ext,
                                         gammas + (long)l*Hc, bmask, bmask == 0);

    // att (float) = probs @ v^T
    gemm_h<<<dim3(1, Sc/128, Bc*Hc), 128>>>(
        S.scores_h, S.v_h, nullptr, S.att, DKc, Sc, SS, SDK, SDK, 1.f, 0, 0);
    from_heads<<<(MROWS*Dc/4)/256, 256>>>(S.att, S.cat_h);

    // output projection + residual LN
    gemm_h<<<dim3(Dc/128, MROWS/128), 128>>>(
        S.cat_h, S.wo + (long)l*DD, ob + (long)l*Dc, S.proj, Dc, Dc, 0, 0, 0, 1.f, 0, 0);
    add_ln<<<MROWS, 256>>>(X, S.proj, ln1g + (long)l*Dc, ln1b + (long)l*Dc, ln1o, ln1o_h);

    if (apply_pos) {
        gemm_h<<<dim3(DFFc/128, MROWS/128), 128>>>(
            S.t1_h, S.w1 + (long)l*DFFc*Dc, b1 + (long)l*DFFc, S.ff_h,
            DFFc, Dc, 0, 0, 0, 1.f, 1, 1);
        gemm_h<<<dim3(Dc/128, MROWS/128), 128>>>(
            S.ff_h, S.w2 + (long)l*Dc*DFFc, b2 + (long)l*Dc, S.proj,
            Dc, DFFc, 0, 0, 0, 1.f, 0, 0);
        add_ln<<<MROWS, 256>>>(S.t1, S.proj, ln2g + (long)l*Dc, ln2b + (long)l*Dc,
                               outbuf, outbuf_h);
    }
}

extern "C" void kernel_launch(void* const* d_in, const int* in_sizes, int n_in,
                              void* d_out, int out_size)
{
    const float* q_embed  = (const float*)d_in[0];
    const float* qa_embed = (const float*)d_in[1];
    const float* kW = (const float*)d_in[2];
    const float* kb = (const float*)d_in[3];
    const float* vW = (const float*)d_in[4];
    const float* vb = (const float*)d_in[5];
    const float* oW = (const float*)d_in[6];
    const float* ob = (const float*)d_in[7];
    const float* gammas = (const float*)d_in[8];
    const float* alphas = (const float*)d_in[9];
    const float* ln1g = (const float*)d_in[10];
    const float* ln1b = (const float*)d_in[11];
    const float* w1 = (const float*)d_in[12];
    const float* b1 = (const float*)d_in[13];
    const float* w2 = (const float*)d_in[14];
    const float* b2 = (const float*)d_in[15];
    const float* ln2g = (const float*)d_in[16];
    const float* ln2b = (const float*)d_in[17];
    const float* gE = (const float*)d_in[18];
    float* out = (float*)d_out;

    Scratch S;
    cudaGetSymbolAddress((void**)&S.wk, g_wk_h);
    cudaGetSymbolAddress((void**)&S.wv, g_wv_h);
    cudaGetSymbolAddress((void**)&S.wo, g_wo_h);
    cudaGetSymbolAddress((void**)&S.w1, g_w1_h);
    cudaGetSymbolAddress((void**)&S.w2, g_w2_h);
    cudaGetSymbolAddress((void**)&S.qa_h, g_qa_h);
    cudaGetSymbolAddress((void**)&S.q_h, g_q_h);
    cudaGetSymbolAddress((void**)&S.y, g_y);
    cudaGetSymbolAddress((void**)&S.y_h, g_y_h);
    cudaGetSymbolAddress((void**)&S.xb, g_xb);
    cudaGetSymbolAddress((void**)&S.xb_h, g_xb_h);
    cudaGetSymbolAddress((void**)&S.t1, g_t1);
    cudaGetSymbolAddress((void**)&S.t1_h, g_t1_h);
    cudaGetSymbolAddress((void**)&S.cat, g_cat);
    cudaGetSymbolAddress((void**)&S.cat_h, g_cat_h);
    cudaGetSymbolAddress((void**)&S.proj, g_proj);
    cudaGetSymbolAddress((void**)&S.qk_h, g_qk_h);
    cudaGetSymbolAddress((void**)&S.v_h, g_v_h);
    cudaGetSymbolAddress((void**)&S.att, g_att);
    cudaGetSymbolAddress((void**)&S.scores, g_scores);
    cudaGetSymbolAddress((void**)&S.scores_h, g_scores_h);
    cudaGetSymbolAddress((void**)&S.ff_h, g_ff_h);
    cudaGetSymbolAddress((void**)&S.ext, g_ext);

    long nDD4 = (long)3 * Dc * Dc / 4;
    long nFF4 = (long)3 * DFFc * Dc / 4;
    long nX4  = (long)MROWS * Dc / 4;
    round_copy_h<<<(int)((nDD4 + 255) / 256), 256>>>(kW, S.wk, nDD4);
    round_copy_h<<<(int)((nDD4 + 255) / 256), 256>>>(vW, S.wv, nDD4);
    round_copy_h<<<(int)((nDD4 + 255) / 256), 256>>>(oW, S.wo, nDD4);
    round_copy_h<<<(int)((nFF4 + 255) / 256), 256>>>(w1, S.w1, nFF4);
    round_copy_h<<<(int)((nFF4 + 255) / 256), 256>>>(w2, S.w2, nFF4);
    round_copy_h<<<(int)((nX4 + 255) / 256), 256>>>(qa_embed, S.qa_h, nX4);
    round_copy_h<<<(int)((nX4 + 255) / 256), 256>>>(q_embed, S.q_h, nX4);

    // layer0: y = L0(qa, qa, qa), bmask=1, FFN
    run_layer(qa_embed, S.qa_h, S.qa_h, S.y, S.y_h, 0, 1, 1,
              kb, vb, ob, gammas, alphas, gE, ln1g, ln1b, b1, b2, ln2g, ln2b, S);
    // layer1: x = L1(q, q, q), bmask=1, no FFN
    run_layer(q_embed, S.q_h, S.q_h, S.xb, S.xb_h, 1, 1, 0,
              kb, vb, ob, gammas, alphas, gE, ln1g, ln1b, b1, b2, ln2g, ln2b, S);
    // layer2: out = L2(x, x, y), bmask=0, FFN
    run_layer(S.xb, S.xb_h, S.y_h, out, nullptr, 2, 0, 1,
              kb, vb, ob, gammas, alphas, gE, ln1g, ln1b, b1, b2, ln2g, ln2b, S);
}